// round 11
// baseline (speedup 1.0000x reference)
#include <cuda_runtime.h>
#include <math.h>

#define NN  50000
#define EE  1250000
#define DIMM 64
#define HHH 16

typedef unsigned long long ull;

// Scratch (device globals).
__device__ float4 g_q [NN * HHH];        // [node][head] 16B
__device__ float4 g_kv[NN * HHH * 2];    // [node][head][{k,v}] 32B per (node,head)
__device__ float  g_dot[NN * DIMM];
__device__ float4 g_agg[NN * HHH];

// ---------------- packed f32x2 helpers (SASS FFMA2) -------------------------
__device__ __forceinline__ void ffma2(ull &acc, ull a, ull b) {
    asm("fma.rn.f32x2 %0, %1, %2, %0;" : "+l"(acc) : "l"(a), "l"(b));
}
__device__ __forceinline__ ull pack2(float a, float b) {
    ull r; asm("mov.b64 %0, {%1,%2};" : "=l"(r) : "f"(a), "f"(b)); return r;
}
__device__ __forceinline__ float sum2(ull v) {
    float a, b; asm("mov.b64 {%0,%1}, %2;" : "=f"(a), "=f"(b) : "l"(v));
    return a + b;
}

// ---------------------------------------------------------------------------
// K1: LayerNorm + QKV. 192 threads (one per output col), 8 nodes/iter.
// grid 1250 x 5 x 8 = 50000.
// ---------------------------------------------------------------------------
#define QKV_GRID 1250
#define QKV_IT   5

__global__ void __launch_bounds__(192, 4) qkv_kernel(
    const float* __restrict__ node_feat,
    const float* __restrict__ ln_g,  const float* __restrict__ ln_b,
    const float* __restrict__ qkv_w, const float* __restrict__ qkv_b)
{
    __shared__ __align__(16) ulonglong2 spw[16 * 192];   // 48 KB packed weights
    __shared__ __align__(16) float s_x [8][64];
    __shared__ __align__(16) float s_xn[8][64];
    __shared__ float s_g[64], s_b[64];
    __shared__ float s_mu[8], s_rs[8];
    const int t = threadIdx.x;  // 0..191

#pragma unroll
    for (int kp = 0; kp < 16; kp++) {
        ulonglong2 p;
        p.x = pack2(qkv_w[(4 * kp    ) * 192 + t], qkv_w[(4 * kp + 1) * 192 + t]);
        p.y = pack2(qkv_w[(4 * kp + 2) * 192 + t], qkv_w[(4 * kp + 3) * 192 + t]);
        spw[kp * 192 + t] = p;
    }
    const float bc = qkv_b[t];
    if (t < 64) { s_g[t] = ln_g[t]; s_b[t] = ln_b[t]; }

    const int h = t / 12;
    const int r = t % 12;
    float* wbase;
    int    wmul, wd;
    if (r < 4) { wbase = (float*)g_q;  wmul = 4; wd = r; }
    else       { wbase = (float*)g_kv; wmul = 8; wd = r - 4; }  // k:0-3, v:4-7
    __syncthreads();

    for (int it = 0; it < QKV_IT; it++) {
        const int n0 = (blockIdx.x + it * QKV_GRID) * 8;

        for (int i = t; i < 512; i += 192)
            ((float*)s_x)[i] = node_feat[n0 * 64 + i];
        __syncthreads();

        if (t < 128) {
            const int nd = t >> 4, l = t & 15;
            const float4 v = *(const float4*)&s_x[nd][l * 4];
            float s  = v.x + v.y + v.z + v.w;
            float s2 = v.x * v.x + v.y * v.y + v.z * v.z + v.w * v.w;
#pragma unroll
            for (int o = 8; o >= 1; o >>= 1) {
                s  += __shfl_xor_sync(0xffffffffu, s,  o);
                s2 += __shfl_xor_sync(0xffffffffu, s2, o);
            }
            if (l == 0) {
                const float mu  = s * (1.f / 64.f);
                const float var = s2 * (1.f / 64.f) - mu * mu;
                s_mu[nd] = mu;
                s_rs[nd] = rsqrtf(var + 1e-5f);
            }
        }
        __syncthreads();

        for (int i = t; i < 512; i += 192) {
            const int nd = i >> 6, k = i & 63;
            ((float*)s_xn)[i] = (((float*)s_x)[i] - s_mu[nd]) * s_rs[nd] * s_g[k] + s_b[k];
        }
        __syncthreads();

        ull acc[8];
#pragma unroll
        for (int nd = 0; nd < 8; nd++) acc[nd] = 0;
        const ulonglong2* xn4 = (const ulonglong2*)s_xn;   // 16 per node
#pragma unroll
        for (int kp = 0; kp < 16; kp++) {
            const ulonglong2 w = spw[kp * 192 + t];
#pragma unroll
            for (int nd = 0; nd < 8; nd++) {
                const ulonglong2 v = xn4[nd * 16 + kp];
                ffma2(acc[nd], v.x, w.x);
                ffma2(acc[nd], v.y, w.y);
            }
        }
#pragma unroll
        for (int nd = 0; nd < 8; nd++)
            wbase[((n0 + nd) * 16 + h) * wmul + wd] = sum2(acc[nd]) + bc;
        __syncthreads();
    }
}

// ---------------------------------------------------------------------------
// K2: iv = node_vec @ vec_w ; input_dot. 128 threads, 4 nodes/iter.
// grid 1250 x 10 x 4 = 50000.  (side stream, hidden under zero+qkv+edge)
// ---------------------------------------------------------------------------
#define VEC_GRID 1250
#define VEC_IT   10

__global__ void __launch_bounds__(128, 6) vec_kernel(
    const float* __restrict__ node_vec,
    const float* __restrict__ vec_w)
{
    __shared__ __align__(16) ulonglong2 spw[16 * 128];   // 32 KB
    __shared__ __align__(16) float s_nv[4][192];
    __shared__ __align__(16) float s_iv[4][3][128];
    const int t = threadIdx.x;

#pragma unroll
    for (int kp = 0; kp < 16; kp++) {
        ulonglong2 p;
        p.x = pack2(vec_w[(4 * kp    ) * 128 + t], vec_w[(4 * kp + 1) * 128 + t]);
        p.y = pack2(vec_w[(4 * kp + 2) * 128 + t], vec_w[(4 * kp + 3) * 128 + t]);
        spw[kp * 128 + t] = p;
    }
    __syncthreads();

    for (int it = 0; it < VEC_IT; it++) {
        const int n0 = (blockIdx.x + it * VEC_GRID) * 4;

        for (int i = t; i < 768; i += 128)
            ((float*)s_nv)[i] = node_vec[n0 * 192 + i];
        __syncthreads();

        ull acc[12];
#pragma unroll
        for (int c = 0; c < 12; c++) acc[c] = 0;
        const ulonglong2* nv4 = (const ulonglong2*)s_nv;  // 16 per chain
#pragma unroll
        for (int kp = 0; kp < 16; kp++) {
            const ulonglong2 w = spw[kp * 128 + t];
#pragma unroll
            for (int c = 0; c < 12; c++) {
                const ulonglong2 v = nv4[c * 16 + kp];
                ffma2(acc[c], v.x, w.x);
                ffma2(acc[c], v.y, w.y);
            }
        }
#pragma unroll
        for (int nd = 0; nd < 4; nd++)
#pragma unroll
            for (int a = 0; a < 3; a++)
                s_iv[nd][a][t] = sum2(acc[nd * 3 + a]);
        __syncthreads();

        if (t < 64) {
#pragma unroll
            for (int nd = 0; nd < 4; nd++) {
                float d = 0.f;
#pragma unroll
                for (int a = 0; a < 3; a++)
                    d += s_iv[nd][a][t] * s_iv[nd][a][64 + t];
                g_dot[(n0 + nd) * 64 + t] = d;
            }
        }
        __syncthreads();
    }
}

// ---------------------------------------------------------------------------
// Kz: zero the aggregation buffer
// ---------------------------------------------------------------------------
__global__ void zero_kernel()
{
    const int i = blockIdx.x * blockDim.x + threadIdx.x;
    if (i < NN * HHH) g_agg[i] = make_float4(0.f, 0.f, 0.f, 0.f);
}

// ---------------------------------------------------------------------------
// K3: edge phase. TWO (edge,head) items per thread (i and i+HALF) for MLP.
// k|v fused gather (32B sector), vector atomics.
// ---------------------------------------------------------------------------
#define EH_TOTAL (EE * HHH)          // 20,000,000
#define EH_HALF  (EH_TOTAL / 2)      // 10,000,000

__global__ void __launch_bounds__(256) edge_kernel(
    const float4* __restrict__ edge_feat,
    const float*  __restrict__ radial,
    const int*    __restrict__ row,
    const int*    __restrict__ col)
{
    const int i = blockIdx.x * blockDim.x + threadIdx.x;
    if (i >= EH_HALF) return;
    const int e1 = i >> 4,             h1 = i & 15;
    const int e2 = (i + EH_HALF) >> 4, h2 = i & 15;   // same h, distant edge

    // interleave both items' loads for MLP
    const int r1 = __ldcs(&row[e1]);
    const int r2 = __ldcs(&row[e2]);
    const int c1 = __ldcs(&col[e1]);
    const int c2 = __ldcs(&col[e2]);

    const float4 qv1 = __ldg(&g_q[r1 * 16 + h1]);
    const float4 qv2 = __ldg(&g_q[r2 * 16 + h2]);
    const float4 kv1 = __ldg(&g_kv[(c1 * 16 + h1) * 2]);
    const float4 kv2 = __ldg(&g_kv[(c2 * 16 + h2) * 2]);
    const float4 vv1 = __ldg(&g_kv[(c1 * 16 + h1) * 2 + 1]);
    const float4 vv2 = __ldg(&g_kv[(c2 * 16 + h2) * 2 + 1]);
    const float  ra1 = __ldcs(&radial[e1]);
    const float  ra2 = __ldcs(&radial[e2]);
    const float4 ef1 = __ldcs(&edge_feat[e1 * 16 + h1]);
    const float4 ef2 = __ldcs(&edge_feat[e2 * 16 + h2]);

    const float dot1 = qv1.x * kv1.x + qv1.y * kv1.y + qv1.z * kv1.z + qv1.w * kv1.w;
    const float dot2 = qv2.x * kv2.x + qv2.y * kv2.y + qv2.z * kv2.z + qv2.w * kv2.w;

    // exact GELU: 0.5*x*(1+erf(x/sqrt(2)))
    const float attn1 = 0.5f * dot1 * (1.f + erff(dot1 * 0.70710678118654752f)) * ra1;
    const float attn2 = 0.5f * dot2 * (1.f + erff(dot2 * 0.70710678118654752f)) * ra2;

    float4* agg1 = &g_agg[r1 * 16 + h1];
    asm volatile("red.global.add.v4.f32 [%0], {%1, %2, %3, %4};"
                 :: "l"(agg1),
                    "f"(vv1.x * ef1.x * attn1), "f"(vv1.y * ef1.y * attn1),
                    "f"(vv1.z * ef1.z * attn1), "f"(vv1.w * ef1.w * attn1)
                 : "memory");
    float4* agg2 = &g_agg[r2 * 16 + h2];
    asm volatile("red.global.add.v4.f32 [%0], {%1, %2, %3, %4};"
                 :: "l"(agg2),
                    "f"(vv2.x * ef2.x * attn2), "f"(vv2.y * ef2.y * attn2),
                    "f"(vv2.z * ef2.z * attn2), "f"(vv2.w * ef2.w * attn2)
                 : "memory");
}

// ---------------------------------------------------------------------------
// K4: out = agg @ out_w + out_b ; result = dot * out[:, :64] + out[:, 64:]
// 128 threads, 8 nodes/iter (8 chains). grid 1250 x 5 x 8 = 50000.
// ---------------------------------------------------------------------------
#define OUT_GRID 1250
#define OUT_IT   5

__global__ void __launch_bounds__(128, 6) out_kernel(
    const float* __restrict__ out_w,
    const float* __restrict__ out_b,
    float* __restrict__ out)
{
    __shared__ __align__(16) ulonglong2 spw[16 * 128];   // 32 KB
    __shared__ __align__(16) float s_a[8][64];
    __shared__ __align__(16) float s_o[8][128];
    const int t = threadIdx.x;

#pragma unroll
    for (int kp = 0; kp < 16; kp++) {
        ulonglong2 p;
        p.x = pack2(out_w[(4 * kp    ) * 128 + t], out_w[(4 * kp + 1) * 128 + t]);
        p.y = pack2(out_w[(4 * kp + 2) * 128 + t], out_w[(4 * kp + 3) * 128 + t]);
        spw[kp * 128 + t] = p;
    }
    const float bc = out_b[t];
    __syncthreads();

    const float* agg = (const float*)g_agg;
    for (int it = 0; it < OUT_IT; it++) {
        const int n0 = (blockIdx.x + it * OUT_GRID) * 8;

        for (int i = t; i < 512; i += 128)
            ((float*)s_a)[i] = agg[n0 * 64 + i];
        __syncthreads();

        ull acc[8];
#pragma unroll
        for (int nd = 0; nd < 8; nd++) acc[nd] = 0;
        const ulonglong2* a4 = (const ulonglong2*)s_a;   // 16 per node
#pragma unroll
        for (int kp = 0; kp < 16; kp++) {
            const ulonglong2 w = spw[kp * 128 + t];
#pragma unroll
            for (int nd = 0; nd < 8; nd++) {
                const ulonglong2 v = a4[nd * 16 + kp];
                ffma2(acc[nd], v.x, w.x);
                ffma2(acc[nd], v.y, w.y);
            }
        }
#pragma unroll
        for (int nd = 0; nd < 8; nd++)
            s_o[nd][t] = sum2(acc[nd]) + bc;
        __syncthreads();

        if (t < 64) {
#pragma unroll
            for (int nd = 0; nd < 8; nd++)
                out[(n0 + nd) * 64 + t] =
                    g_dot[(n0 + nd) * 64 + t] * s_o[nd][t] + s_o[nd][64 + t];
        }
        __syncthreads();
    }
}

// ---------------------------------------------------------------------------
// Schedule (fork/join inside graph capture):
//   main stream : zero -> qkv -> edge -> (join) -> out
//   side stream : vec
// ---------------------------------------------------------------------------
extern "C" void kernel_launch(void* const* d_in, const int* in_sizes, int n_in,
                              void* d_out, int out_size)
{
    const float* node_feat = (const float*)d_in[0];
    const float* edge_feat = (const float*)d_in[1];
    const float* node_vec  = (const float*)d_in[2];
    const float* radial    = (const float*)d_in[3];
    const float* ln_g      = (const float*)d_in[4];
    const float* ln_b      = (const float*)d_in[5];
    const float* qkv_w     = (const float*)d_in[6];
    const float* qkv_b     = (const float*)d_in[7];
    const float* vec_w     = (const float*)d_in[8];
    const float* out_w     = (const float*)d_in[9];
    const float* out_b     = (const float*)d_in[10];
    const int*   row       = (const int*)d_in[11];
    const int*   col       = (const int*)d_in[12];
    float*       out       = (float*)d_out;

    static cudaStream_t s_side = nullptr;
    static cudaEvent_t  ev_fork = nullptr, ev_join = nullptr;
    if (s_side == nullptr) {
        cudaStreamCreateWithFlags(&s_side, cudaStreamNonBlocking);
        cudaEventCreateWithFlags(&ev_fork, cudaEventDisableTiming);
        cudaEventCreateWithFlags(&ev_join, cudaEventDisableTiming);
    }

    cudaEventRecord(ev_fork, 0);
    cudaStreamWaitEvent(s_side, ev_fork, 0);

    vec_kernel<<<VEC_GRID, 128, 0, s_side>>>(node_vec, vec_w);

    zero_kernel<<<(NN * HHH + 255) / 256, 256>>>();
    qkv_kernel<<<QKV_GRID, 192>>>(node_feat, ln_g, ln_b, qkv_w, qkv_b);
    edge_kernel<<<(EH_HALF + 255) / 256, 256>>>(
        (const float4*)edge_feat, radial, row, col);

    cudaEventRecord(ev_join, s_side);
    cudaStreamWaitEvent(0, ev_join, 0);

    out_kernel<<<OUT_GRID, 128>>>(out_w, out_b, out);
}

// round 14
// speedup vs baseline: 1.2015x; 1.2015x over previous
#include <cuda_runtime.h>
#include <math.h>

#define NN  50000
#define EE  1250000
#define DIMM 64
#define HHH 16

typedef unsigned long long ull;

// Scratch (device globals).
__device__ float4 g_q [NN * HHH];        // [node][head] 16B
__device__ float4 g_kv[NN * HHH * 2];    // [node][head][{k,v}] 32B per (node,head)
__device__ float  g_dot[NN * DIMM];
__device__ float4 g_agg[NN * HHH];

// ---------------- packed f32x2 helpers (SASS FFMA2) -------------------------
__device__ __forceinline__ void ffma2(ull &acc, ull a, ull b) {
    asm("fma.rn.f32x2 %0, %1, %2, %0;" : "+l"(acc) : "l"(a), "l"(b));
}
__device__ __forceinline__ ull pack2(float a, float b) {
    ull r; asm("mov.b64 %0, {%1,%2};" : "=l"(r) : "f"(a), "f"(b)); return r;
}
__device__ __forceinline__ float sum2(ull v) {
    float a, b; asm("mov.b64 {%0,%1}, %2;" : "=f"(a), "=f"(b) : "l"(v));
    return a + b;
}

// ---------------------------------------------------------------------------
// K1: LayerNorm + QKV. 192 threads = 2 groups x 96; each thread owns 2 cols
// (tg, tg+96); each group does 8 nodes -> 16 nodes/iter.
// grid 625 x 5 x 16 = 50000.
// ---------------------------------------------------------------------------
#define QKV_GRID 625
#define QKV_IT   5

__global__ void __launch_bounds__(192, 4) qkv_kernel(
    const float* __restrict__ node_feat,
    const float* __restrict__ ln_g,  const float* __restrict__ ln_b,
    const float* __restrict__ qkv_w, const float* __restrict__ qkv_b)
{
    __shared__ __align__(16) ulonglong2 spw[16 * 192];   // 48 KB packed weights
    __shared__ __align__(16) float s_x [16][64];
    __shared__ __align__(16) float s_xn[16][64];
    __shared__ float s_g[64], s_b[64];
    __shared__ float s_mu[16], s_rs[16];
    const int t  = threadIdx.x;   // 0..191
    const int g  = t / 96;        // node group
    const int tg = t % 96;        // col base: owns cols tg and tg+96

#pragma unroll
    for (int kp = 0; kp < 16; kp++) {
        ulonglong2 p;
        p.x = pack2(qkv_w[(4 * kp    ) * 192 + t], qkv_w[(4 * kp + 1) * 192 + t]);
        p.y = pack2(qkv_w[(4 * kp + 2) * 192 + t], qkv_w[(4 * kp + 3) * 192 + t]);
        spw[kp * 192 + t] = p;
    }
    const float bc1 = qkv_b[tg];
    const float bc2 = qkv_b[tg + 96];
    if (t < 64) { s_g[t] = ln_g[t]; s_b[t] = ln_b[t]; }

    // output mapping for both cols
    const int c1 = tg, c2 = tg + 96;
    const int h1 = c1 / 12, r1 = c1 % 12;
    const int h2 = c2 / 12, r2 = c2 % 12;
    float *wb1, *wb2; int wm1, wm2, wd1, wd2;
    if (r1 < 4) { wb1 = (float*)g_q;  wm1 = 4; wd1 = r1; }
    else        { wb1 = (float*)g_kv; wm1 = 8; wd1 = r1 - 4; }
    if (r2 < 4) { wb2 = (float*)g_q;  wm2 = 4; wd2 = r2; }
    else        { wb2 = (float*)g_kv; wm2 = 8; wd2 = r2 - 4; }
    __syncthreads();

    for (int it = 0; it < QKV_IT; it++) {
        const int n0 = (blockIdx.x + it * QKV_GRID) * 16;

        for (int i = t; i < 1024; i += 192)
            ((float*)s_x)[i] = node_feat[n0 * 64 + i];
        __syncthreads();

        // LN stats: 16 lanes per node; pass1 nodes 0..11, pass2 nodes 12..15
        {
            const int l = t & 15;
            int nd = t >> 4;                       // 0..11
            for (int pass = 0; pass < 2; pass++) {
                if (pass == 0 || t < 64) {
                    const float4 v = *(const float4*)&s_x[nd][l * 4];
                    float s  = v.x + v.y + v.z + v.w;
                    float s2 = v.x * v.x + v.y * v.y + v.z * v.z + v.w * v.w;
#pragma unroll
                    for (int o = 8; o >= 1; o >>= 1) {
                        s  += __shfl_xor_sync(0xffffffffu, s,  o);
                        s2 += __shfl_xor_sync(0xffffffffu, s2, o);
                    }
                    if (l == 0) {
                        const float mu  = s * (1.f / 64.f);
                        const float var = s2 * (1.f / 64.f) - mu * mu;
                        s_mu[nd] = mu;
                        s_rs[nd] = rsqrtf(var + 1e-5f);
                    }
                }
                nd += 12;
            }
        }
        __syncthreads();

        for (int i = t; i < 1024; i += 192) {
            const int nd = i >> 6, k = i & 63;
            ((float*)s_xn)[i] = (((float*)s_x)[i] - s_mu[nd]) * s_rs[nd] * s_g[k] + s_b[k];
        }
        __syncthreads();

        // GEMM: 8 nodes x 2 cols = 16 chains; each act LDS feeds 4 FFMA2
        ull acc1[8], acc2[8];
#pragma unroll
        for (int nd = 0; nd < 8; nd++) { acc1[nd] = 0; acc2[nd] = 0; }
        const ulonglong2* xn4 = (const ulonglong2*)&s_xn[g * 8][0];  // 16/node
#pragma unroll
        for (int kp = 0; kp < 16; kp++) {
            const ulonglong2 w1 = spw[kp * 192 + tg];
            const ulonglong2 w2 = spw[kp * 192 + tg + 96];
#pragma unroll
            for (int nd = 0; nd < 8; nd++) {
                const ulonglong2 v = xn4[nd * 16 + kp];
                ffma2(acc1[nd], v.x, w1.x);
                ffma2(acc1[nd], v.y, w1.y);
                ffma2(acc2[nd], v.x, w2.x);
                ffma2(acc2[nd], v.y, w2.y);
            }
        }
#pragma unroll
        for (int nd = 0; nd < 8; nd++) {
            const int n = n0 + g * 8 + nd;
            wb1[(n * 16 + h1) * wm1 + wd1] = sum2(acc1[nd]) + bc1;
            wb2[(n * 16 + h2) * wm2 + wd2] = sum2(acc2[nd]) + bc2;
        }
        __syncthreads();
    }
}

// ---------------------------------------------------------------------------
// K2: iv = node_vec @ vec_w ; input_dot. 128 threads = 2 groups x 64;
// thread owns cols (tg, tg+64); group does 2 nodes -> 4 nodes/iter.
// grid 1250 x 10 x 4 = 50000.  (side stream)
// ---------------------------------------------------------------------------
#define VEC_GRID 1250
#define VEC_IT   10

__global__ void __launch_bounds__(128, 5) vec_kernel(
    const float* __restrict__ node_vec,
    const float* __restrict__ vec_w)
{
    __shared__ __align__(16) ulonglong2 spw[16 * 128];   // 32 KB
    __shared__ __align__(16) float s_nv[4][192];
    __shared__ __align__(16) float s_iv[4][3][128];
    const int t  = threadIdx.x;
    const int g  = t >> 6;       // node group (2 nodes each)
    const int tg = t & 63;       // owns cols tg, tg+64

#pragma unroll
    for (int kp = 0; kp < 16; kp++) {
        ulonglong2 p;
        p.x = pack2(vec_w[(4 * kp    ) * 128 + t], vec_w[(4 * kp + 1) * 128 + t]);
        p.y = pack2(vec_w[(4 * kp + 2) * 128 + t], vec_w[(4 * kp + 3) * 128 + t]);
        spw[kp * 128 + t] = p;
    }
    __syncthreads();

    for (int it = 0; it < VEC_IT; it++) {
        const int n0 = (blockIdx.x + it * VEC_GRID) * 4;

        for (int i = t; i < 768; i += 128)
            ((float*)s_nv)[i] = node_vec[n0 * 192 + i];
        __syncthreads();

        // 2 nodes x 3 comps x 2 cols = 12 chains; act LDS feeds 4 FFMA2
        ull acc1[6], acc2[6];                     // [nd*3+a]
#pragma unroll
        for (int c = 0; c < 6; c++) { acc1[c] = 0; acc2[c] = 0; }
        const ulonglong2* nv4 = (const ulonglong2*)&s_nv[g * 2][0];
#pragma unroll
        for (int kp = 0; kp < 16; kp++) {
            const ulonglong2 w1 = spw[kp * 128 + tg];
            const ulonglong2 w2 = spw[kp * 128 + tg + 64];
#pragma unroll
            for (int c = 0; c < 6; c++) {         // c = nd*3 + a
                const ulonglong2 v = nv4[c * 16 + kp];
                ffma2(acc1[c], v.x, w1.x);
                ffma2(acc1[c], v.y, w1.y);
                ffma2(acc2[c], v.x, w2.x);
                ffma2(acc2[c], v.y, w2.y);
            }
        }
#pragma unroll
        for (int nd = 0; nd < 2; nd++)
#pragma unroll
            for (int a = 0; a < 3; a++) {
                s_iv[g * 2 + nd][a][tg]      = sum2(acc1[nd * 3 + a]);
                s_iv[g * 2 + nd][a][tg + 64] = sum2(acc2[nd * 3 + a]);
            }
        __syncthreads();

        if (t < 64) {
#pragma unroll
            for (int nd = 0; nd < 4; nd++) {
                float d = 0.f;
#pragma unroll
                for (int a = 0; a < 3; a++)
                    d += s_iv[nd][a][t] * s_iv[nd][a][64 + t];
                g_dot[(n0 + nd) * 64 + t] = d;
            }
        }
        __syncthreads();
    }
}

// ---------------------------------------------------------------------------
// Kz: zero the aggregation buffer
// ---------------------------------------------------------------------------
__global__ void zero_kernel()
{
    const int i = blockIdx.x * blockDim.x + threadIdx.x;
    if (i < NN * HHH) g_agg[i] = make_float4(0.f, 0.f, 0.f, 0.f);
}

// ---------------------------------------------------------------------------
// K3: edge phase (R10 form). One thread per (edge, head). k|v fused gather,
// vector atomics.
// ---------------------------------------------------------------------------
__global__ void __launch_bounds__(256) edge_kernel(
    const float4* __restrict__ edge_feat,
    const float*  __restrict__ radial,
    const int*    __restrict__ row,
    const int*    __restrict__ col)
{
    const int gid = blockIdx.x * blockDim.x + threadIdx.x;
    if (gid >= EE * HHH) return;
    const int e = gid >> 4;
    const int h = gid & 15;

    const int r = __ldcs(&row[e]);
    const int c = __ldcs(&col[e]);

    const float4 qv = __ldg(&g_q[r * 16 + h]);
    const float4 kv = __ldg(&g_kv[(c * 16 + h) * 2]);
    const float4 vv = __ldg(&g_kv[(c * 16 + h) * 2 + 1]);

    const float dot = qv.x * kv.x + qv.y * kv.y + qv.z * kv.z + qv.w * kv.w;

    // exact GELU: 0.5*x*(1+erf(x/sqrt(2)))
    const float attn = 0.5f * dot * (1.f + erff(dot * 0.70710678118654752f))
                     * __ldcs(&radial[e]);

    const float4 ef = __ldcs(&edge_feat[e * 16 + h]);

    float4* agg = &g_agg[r * 16 + h];
    asm volatile("red.global.add.v4.f32 [%0], {%1, %2, %3, %4};"
                 :: "l"(agg),
                    "f"(vv.x * ef.x * attn), "f"(vv.y * ef.y * attn),
                    "f"(vv.z * ef.z * attn), "f"(vv.w * ef.w * attn)
                 : "memory");
}

// ---------------------------------------------------------------------------
// K4: out GEMM + combine. 128 threads = 2 groups x 64; thread owns cols
// (tg, tg+64); group does 8 nodes -> 16 nodes/iter. grid 625 x 5 x 16.
// ---------------------------------------------------------------------------
#define OUT_GRID 625
#define OUT_IT   5

__global__ void __launch_bounds__(128, 5) out_kernel(
    const float* __restrict__ out_w,
    const float* __restrict__ out_b,
    float* __restrict__ out)
{
    __shared__ __align__(16) ulonglong2 spw[16 * 128];   // 32 KB
    __shared__ __align__(16) float s_a[16][64];
    __shared__ __align__(16) float s_o[16][128];
    const int t  = threadIdx.x;
    const int g  = t >> 6;
    const int tg = t & 63;

#pragma unroll
    for (int kp = 0; kp < 16; kp++) {
        ulonglong2 p;
        p.x = pack2(out_w[(4 * kp    ) * 128 + t], out_w[(4 * kp + 1) * 128 + t]);
        p.y = pack2(out_w[(4 * kp + 2) * 128 + t], out_w[(4 * kp + 3) * 128 + t]);
        spw[kp * 128 + t] = p;
    }
    const float bc1 = out_b[tg];
    const float bc2 = out_b[tg + 64];
    __syncthreads();

    const float* agg = (const float*)g_agg;
    for (int it = 0; it < OUT_IT; it++) {
        const int n0 = (blockIdx.x + it * OUT_GRID) * 16;

        for (int i = t; i < 1024; i += 128)
            ((float*)s_a)[i] = agg[n0 * 64 + i];
        __syncthreads();

        // 8 nodes x 2 cols = 16 chains
        ull acc1[8], acc2[8];
#pragma unroll
        for (int nd = 0; nd < 8; nd++) { acc1[nd] = 0; acc2[nd] = 0; }
        const ulonglong2* a4 = (const ulonglong2*)&s_a[g * 8][0];   // 16/node
#pragma unroll
        for (int kp = 0; kp < 16; kp++) {
            const ulonglong2 w1 = spw[kp * 128 + tg];
            const ulonglong2 w2 = spw[kp * 128 + tg + 64];
#pragma unroll
            for (int nd = 0; nd < 8; nd++) {
                const ulonglong2 v = a4[nd * 16 + kp];
                ffma2(acc1[nd], v.x, w1.x);
                ffma2(acc1[nd], v.y, w1.y);
                ffma2(acc2[nd], v.x, w2.x);
                ffma2(acc2[nd], v.y, w2.y);
            }
        }
#pragma unroll
        for (int nd = 0; nd < 8; nd++) {
            s_o[g * 8 + nd][tg]      = sum2(acc1[nd]) + bc1;
            s_o[g * 8 + nd][tg + 64] = sum2(acc2[nd]) + bc2;
        }
        __syncthreads();

        for (int i = t; i < 1024; i += 128) {
            const int nd = i >> 6, k = i & 63;
            out[(n0 + nd) * 64 + k] =
                g_dot[(n0 + nd) * 64 + k] * s_o[nd][k] + s_o[nd][64 + k];
        }
        __syncthreads();
    }
}

// ---------------------------------------------------------------------------
// Schedule (fork/join inside graph capture):
//   main stream : zero -> qkv -> edge -> (join) -> out
//   side stream : vec
// ---------------------------------------------------------------------------
extern "C" void kernel_launch(void* const* d_in, const int* in_sizes, int n_in,
                              void* d_out, int out_size)
{
    const float* node_feat = (const float*)d_in[0];
    const float* edge_feat = (const float*)d_in[1];
    const float* node_vec  = (const float*)d_in[2];
    const float* radial    = (const float*)d_in[3];
    const float* ln_g      = (const float*)d_in[4];
    const float* ln_b      = (const float*)d_in[5];
    const float* qkv_w     = (const float*)d_in[6];
    const float* qkv_b     = (const float*)d_in[7];
    const float* vec_w     = (const float*)d_in[8];
    const float* out_w     = (const float*)d_in[9];
    const float* out_b     = (const float*)d_in[10];
    const int*   row       = (const int*)d_in[11];
    const int*   col       = (const int*)d_in[12];
    float*       out       = (float*)d_out;

    static cudaStream_t s_side = nullptr;
    static cudaEvent_t  ev_fork = nullptr, ev_join = nullptr;
    if (s_side == nullptr) {
        cudaStreamCreateWithFlags(&s_side, cudaStreamNonBlocking);
        cudaEventCreateWithFlags(&ev_fork, cudaEventDisableTiming);
        cudaEventCreateWithFlags(&ev_join, cudaEventDisableTiming);
    }

    cudaEventRecord(ev_fork, 0);
    cudaStreamWaitEvent(s_side, ev_fork, 0);

    vec_kernel<<<VEC_GRID, 128, 0, s_side>>>(node_vec, vec_w);

    zero_kernel<<<(NN * HHH + 255) / 256, 256>>>();
    qkv_kernel<<<QKV_GRID, 192>>>(node_feat, ln_g, ln_b, qkv_w, qkv_b);
    edge_kernel<<<(EE * HHH + 255) / 256, 256>>>(
        (const float4*)edge_feat, radial, row, col);

    cudaEventRecord(ev_join, s_side);
    cudaStreamWaitEvent(0, ev_join, 0);

    out_kernel<<<OUT_GRID, 128>>>(out_w, out_b, out);
}